// round 1
// baseline (speedup 1.0000x reference)
#include <cuda_runtime.h>
#include <math.h>

#define NSEQ  256
#define LRES  384
#define MDIM  256
#define NHEAD 8
#define CDIM  32
#define HC    256
#define NL    (NSEQ * LRES)            // 98304
#define SQC   0.17677669529663687f     // 1/sqrt(32)

// -------- scratch (static device globals; no allocations allowed) --------
__device__ float g_x[(size_t)NL * MDIM];   // layernormed input
__device__ float g_q[(size_t)NL * HC];
__device__ float g_k[(size_t)NL * HC];
__device__ float g_v[(size_t)NL * HC];
__device__ float g_g[(size_t)NL * HC];     // sigmoid gate (activation applied)
__device__ float g_o[(size_t)NL * HC];     // gated attention output

// ============================ LayerNorm ============================
// one block (64 threads) per row of 256; float4 per thread
__global__ void ln_kernel(const float* __restrict__ m,
                          const float* __restrict__ gamma,
                          const float* __restrict__ beta) {
    int row = blockIdx.x;
    const float4* mr = (const float4*)(m + (size_t)row * MDIM);
    float4* xr = (float4*)(g_x + (size_t)row * MDIM);
    int tid = threadIdx.x;

    float4 v = mr[tid];
    float s  = v.x + v.y + v.z + v.w;
    float ss = v.x * v.x + v.y * v.y + v.z * v.z + v.w * v.w;
    #pragma unroll
    for (int o = 16; o; o >>= 1) {
        s  += __shfl_xor_sync(0xffffffffu, s,  o);
        ss += __shfl_xor_sync(0xffffffffu, ss, o);
    }
    __shared__ float sh[4];
    if ((tid & 31) == 0) { sh[tid >> 5] = s; sh[2 + (tid >> 5)] = ss; }
    __syncthreads();
    s  = sh[0] + sh[1];
    ss = sh[2] + sh[3];
    float mu  = s * (1.0f / MDIM);
    float var = ss * (1.0f / MDIM) - mu * mu;
    float inv = rsqrtf(var + 1e-5f);

    float4 gm = ((const float4*)gamma)[tid];
    float4 bt = ((const float4*)beta)[tid];
    float4 r;
    r.x = (v.x - mu) * inv * gm.x + bt.x;
    r.y = (v.y - mu) * inv * gm.y + bt.y;
    r.z = (v.z - mu) * inv * gm.z + bt.z;
    r.w = (v.w - mu) * inv * gm.w + bt.w;
    xr[tid] = r;
}

// ============================ GEMM ============================
// C[M,256] = A[M,256] * B[256,256]   (A,B,C row-major)
// epi_mode: 0 plain, 1 sigmoid(v + bias), 2 v + bias
#define BM 64
#define BN 64
#define BK 16
__global__ void gemm_kernel(const float* __restrict__ A,
                            const float* __restrict__ B,
                            const float* __restrict__ bias,
                            float* __restrict__ Cout,
                            int epi_mode) {
    __shared__ float As[BK][BM];
    __shared__ float Bs[BK][BN];

    int bn = blockIdx.x * BN;
    int bm = blockIdx.y * BM;
    int tid = threadIdx.x;                 // 256 threads
    int tx = tid & 15, ty = tid >> 4;

    float acc[4][4] = {};

    int ar = tid >> 2;                     // 0..63 (A row within tile)
    int ac = (tid & 3) << 2;               // 0,4,8,12 (A k-offset)
    int br = tid >> 4;                     // 0..15 (B k within tile)
    int bc = (tid & 15) << 2;              // B col offset

    for (int k0 = 0; k0 < 256; k0 += BK) {
        float4 a4 = *(const float4*)&A[(size_t)(bm + ar) * 256 + k0 + ac];
        As[ac + 0][ar] = a4.x;
        As[ac + 1][ar] = a4.y;
        As[ac + 2][ar] = a4.z;
        As[ac + 3][ar] = a4.w;
        *(float4*)&Bs[br][bc] = *(const float4*)&B[(size_t)(k0 + br) * 256 + bn + bc];
        __syncthreads();

        #pragma unroll
        for (int kk = 0; kk < BK; kk++) {
            float4 a = *(float4*)&As[kk][ty << 2];
            float4 b = *(float4*)&Bs[kk][tx << 2];
            acc[0][0] += a.x * b.x; acc[0][1] += a.x * b.y; acc[0][2] += a.x * b.z; acc[0][3] += a.x * b.w;
            acc[1][0] += a.y * b.x; acc[1][1] += a.y * b.y; acc[1][2] += a.y * b.z; acc[1][3] += a.y * b.w;
            acc[2][0] += a.z * b.x; acc[2][1] += a.z * b.y; acc[2][2] += a.z * b.z; acc[2][3] += a.z * b.w;
            acc[3][0] += a.w * b.x; acc[3][1] += a.w * b.y; acc[3][2] += a.w * b.z; acc[3][3] += a.w * b.w;
        }
        __syncthreads();
    }

    #pragma unroll
    for (int i = 0; i < 4; i++) {
        int row = bm + (ty << 2) + i;
        #pragma unroll
        for (int j = 0; j < 4; j++) {
            int col = bn + (tx << 2) + j;
            float val = acc[i][j];
            if (epi_mode == 1)      val = 1.0f / (1.0f + expf(-(val + bias[col])));
            else if (epi_mode == 2) val += bias[col];
            Cout[(size_t)row * 256 + col] = val;
        }
    }
}

// ============================ Attention ============================
// one CTA (256 threads = 8 warps) per (l, h). K and V^T resident in smem.
#define KST 36        // k_sm row stride (floats) — conflict-free float4 reads
#define VST 260       // v^T row stride
#define PST 260       // per-warp softmax prob stride

#define K_SM_F  (256 * KST)                       // 9216
#define V_SM_F  (32 * VST)                        // 8320
#define P_SM_F  (8 * PST)                         // 2080
#define Q_SM_F  (8 * 32)                          // 256
#define ATTN_SMEM_BYTES ((K_SM_F + V_SM_F + P_SM_F + Q_SM_F) * 4)   // 79488

__global__ void attn_kernel() {
    extern __shared__ float sm[];
    float* k_sm = sm;
    float* v_sm = sm + K_SM_F;
    float* p_sm = sm + K_SM_F + V_SM_F;
    float* q_sm = sm + K_SM_F + V_SM_F + P_SM_F;

    int l = blockIdx.x >> 3;
    int h = blockIdx.x & 7;
    int tid = threadIdx.x;
    int w = tid >> 5, lane = tid & 31;

    size_t head_off = (size_t)h * CDIM;

    // load K (256 x 32) and V^T (32 x 256) into smem
    for (int idx = tid; idx < 256 * 32; idx += 256) {
        int t = idx >> 5, c = idx & 31;
        size_t gi = ((size_t)(t * LRES + l)) * HC + head_off + c;
        k_sm[t * KST + c] = g_k[gi];
        v_sm[c * VST + t] = g_v[gi];
    }
    __syncthreads();

    // each warp owns query rows s = w, w+8, ...
    for (int s = w; s < NSEQ; s += 8) {
        size_t qi = ((size_t)(s * LRES + l)) * HC + head_off + lane;
        q_sm[w * 32 + lane] = g_q[qi];
        __syncwarp();

        float sc[8];
        #pragma unroll
        for (int i = 0; i < 8; i++) {
            int t = i * 32 + lane;
            float acc = 0.0f;
            #pragma unroll
            for (int c4 = 0; c4 < 8; c4++) {
                float4 k4 = *(float4*)&k_sm[t * KST + c4 * 4];
                float4 q4 = *(float4*)&q_sm[w * 32 + c4 * 4];
                acc += k4.x * q4.x + k4.y * q4.y + k4.z * q4.z + k4.w * q4.w;
            }
            sc[i] = acc * SQC;
        }
        // softmax over t (256 values spread 8-per-lane)
        float mx = sc[0];
        #pragma unroll
        for (int i = 1; i < 8; i++) mx = fmaxf(mx, sc[i]);
        #pragma unroll
        for (int o = 16; o; o >>= 1) mx = fmaxf(mx, __shfl_xor_sync(0xffffffffu, mx, o));
        float sum = 0.0f;
        #pragma unroll
        for (int i = 0; i < 8; i++) { sc[i] = __expf(sc[i] - mx); sum += sc[i]; }
        #pragma unroll
        for (int o = 16; o; o >>= 1) sum += __shfl_xor_sync(0xffffffffu, sum, o);
        float rinv = 1.0f / sum;
        #pragma unroll
        for (int i = 0; i < 8; i++) p_sm[w * PST + i * 32 + lane] = sc[i] * rinv;
        __syncwarp();

        // out: lane = channel c;  o[c] = sum_t p[t] * v[t][c]
        float acc = 0.0f;
        #pragma unroll
        for (int t4 = 0; t4 < 64; t4++) {
            float4 p4 = *(float4*)&p_sm[w * PST + t4 * 4];
            float4 v4 = *(float4*)&v_sm[lane * VST + t4 * 4];
            acc += p4.x * v4.x + p4.y * v4.y + p4.z * v4.z + p4.w * v4.w;
        }
        float gv = g_g[qi];
        g_o[qi] = acc * gv;
        __syncwarp();
    }
}

// ============================ launch ============================
extern "C" void kernel_launch(void* const* d_in, const int* in_sizes, int n_in,
                              void* d_out, int out_size) {
    (void)in_sizes; (void)n_in; (void)out_size;
    const float* m     = (const float*)d_in[0];
    const float* gamma = (const float*)d_in[1];
    const float* beta  = (const float*)d_in[2];
    const float* Wq    = (const float*)d_in[3];
    const float* Wk    = (const float*)d_in[4];
    const float* Wv    = (const float*)d_in[5];
    const float* Wg    = (const float*)d_in[6];
    const float* bg    = (const float*)d_in[7];
    const float* Wo    = (const float*)d_in[8];
    const float* bo    = (const float*)d_in[9];
    float* out = (float*)d_out;

    float *x, *q, *k, *v, *g, *o;
    cudaGetSymbolAddress((void**)&x, g_x);
    cudaGetSymbolAddress((void**)&q, g_q);
    cudaGetSymbolAddress((void**)&k, g_k);
    cudaGetSymbolAddress((void**)&v, g_v);
    cudaGetSymbolAddress((void**)&g, g_g);
    cudaGetSymbolAddress((void**)&o, g_o);

    cudaFuncSetAttribute(attn_kernel, cudaFuncAttributeMaxDynamicSharedMemorySize,
                         ATTN_SMEM_BYTES);

    // 1) layernorm
    ln_kernel<<<NL, 64>>>(m, gamma, beta);

    // 2) projections (q, k, v plain; g with sigmoid+bias)
    dim3 ggrid(256 / BN, NL / BM);
    gemm_kernel<<<ggrid, 256>>>(x, Wq, nullptr, q, 0);
    gemm_kernel<<<ggrid, 256>>>(x, Wk, nullptr, k, 0);
    gemm_kernel<<<ggrid, 256>>>(x, Wv, nullptr, v, 0);
    gemm_kernel<<<ggrid, 256>>>(x, Wg, bg,      g, 1);

    // 3) attention per (l, h)
    attn_kernel<<<LRES * NHEAD, 256, ATTN_SMEM_BYTES>>>();

    // 4) output projection + bias
    gemm_kernel<<<ggrid, 256>>>(o, Wo, bo, out, 2);
}

// round 2
// speedup vs baseline: 1.0006x; 1.0006x over previous
#include <cuda_runtime.h>
#include <math.h>

#define NSEQ  256
#define LRES  384
#define MDIM  256
#define NHEAD 8
#define CDIM  32
#define HC    256
#define NL    (NSEQ * LRES)            // 98304
#define SQC   0.17677669529663687f     // 1/sqrt(32)

// -------- scratch (static device globals; no allocations allowed) --------
__device__ float g_x[(size_t)NL * MDIM];   // layernormed input
__device__ float g_q[(size_t)NL * HC];
__device__ float g_k[(size_t)NL * HC];
__device__ float g_v[(size_t)NL * HC];
__device__ float g_g[(size_t)NL * HC];     // sigmoid gate (activation applied)
__device__ float g_o[(size_t)NL * HC];     // gated attention output

// ============================ LayerNorm ============================
// one block (64 threads) per row of 256; float4 per thread
__global__ void ln_kernel(const float* __restrict__ m,
                          const float* __restrict__ gamma,
                          const float* __restrict__ beta) {
    int row = blockIdx.x;
    const float4* mr = (const float4*)(m + (size_t)row * MDIM);
    float4* xr = (float4*)(g_x + (size_t)row * MDIM);
    int tid = threadIdx.x;

    float4 v = mr[tid];
    float s  = v.x + v.y + v.z + v.w;
    float ss = v.x * v.x + v.y * v.y + v.z * v.z + v.w * v.w;
    #pragma unroll
    for (int o = 16; o; o >>= 1) {
        s  += __shfl_xor_sync(0xffffffffu, s,  o);
        ss += __shfl_xor_sync(0xffffffffu, ss, o);
    }
    __shared__ float sh[4];
    if ((tid & 31) == 0) { sh[tid >> 5] = s; sh[2 + (tid >> 5)] = ss; }
    __syncthreads();
    s  = sh[0] + sh[1];
    ss = sh[2] + sh[3];
    float mu  = s * (1.0f / MDIM);
    float var = ss * (1.0f / MDIM) - mu * mu;
    float inv = rsqrtf(var + 1e-5f);

    float4 gm = ((const float4*)gamma)[tid];
    float4 bt = ((const float4*)beta)[tid];
    float4 r;
    r.x = (v.x - mu) * inv * gm.x + bt.x;
    r.y = (v.y - mu) * inv * gm.y + bt.y;
    r.z = (v.z - mu) * inv * gm.z + bt.z;
    r.w = (v.w - mu) * inv * gm.w + bt.w;
    xr[tid] = r;
}

// ============================ GEMM ============================
// C[M,256] = A[M,256] * B[256,256]   (A,B,C row-major)
// epi_mode: 0 plain, 1 sigmoid(v + bias), 2 v + bias
#define BM 64
#define BN 64
#define BK 16
__global__ void gemm_kernel(const float* __restrict__ A,
                            const float* __restrict__ B,
                            const float* __restrict__ bias,
                            float* __restrict__ Cout,
                            int epi_mode) {
    __shared__ float As[BK][BM];
    __shared__ float Bs[BK][BN];

    int bn = blockIdx.x * BN;
    int bm = blockIdx.y * BM;
    int tid = threadIdx.x;                 // 256 threads
    int tx = tid & 15, ty = tid >> 4;

    float acc[4][4] = {};

    int ar = tid >> 2;                     // 0..63 (A row within tile)
    int ac = (tid & 3) << 2;               // 0,4,8,12 (A k-offset)
    int br = tid >> 4;                     // 0..15 (B k within tile)
    int bc = (tid & 15) << 2;              // B col offset

    for (int k0 = 0; k0 < 256; k0 += BK) {
        float4 a4 = *(const float4*)&A[(size_t)(bm + ar) * 256 + k0 + ac];
        As[ac + 0][ar] = a4.x;
        As[ac + 1][ar] = a4.y;
        As[ac + 2][ar] = a4.z;
        As[ac + 3][ar] = a4.w;
        *(float4*)&Bs[br][bc] = *(const float4*)&B[(size_t)(k0 + br) * 256 + bn + bc];
        __syncthreads();

        #pragma unroll
        for (int kk = 0; kk < BK; kk++) {
            float4 a = *(float4*)&As[kk][ty << 2];
            float4 b = *(float4*)&Bs[kk][tx << 2];
            acc[0][0] += a.x * b.x; acc[0][1] += a.x * b.y; acc[0][2] += a.x * b.z; acc[0][3] += a.x * b.w;
            acc[1][0] += a.y * b.x; acc[1][1] += a.y * b.y; acc[1][2] += a.y * b.z; acc[1][3] += a.y * b.w;
            acc[2][0] += a.z * b.x; acc[2][1] += a.z * b.y; acc[2][2] += a.z * b.z; acc[2][3] += a.z * b.w;
            acc[3][0] += a.w * b.x; acc[3][1] += a.w * b.y; acc[3][2] += a.w * b.z; acc[3][3] += a.w * b.w;
        }
        __syncthreads();
    }

    #pragma unroll
    for (int i = 0; i < 4; i++) {
        int row = bm + (ty << 2) + i;
        #pragma unroll
        for (int j = 0; j < 4; j++) {
            int col = bn + (tx << 2) + j;
            float val = acc[i][j];
            if (epi_mode == 1)      val = 1.0f / (1.0f + expf(-(val + bias[col])));
            else if (epi_mode == 2) val += bias[col];
            Cout[(size_t)row * 256 + col] = val;
        }
    }
}

// ============================ Attention ============================
// one CTA (256 threads = 8 warps) per (l, h). K and V^T resident in smem.
#define KST 36        // k_sm row stride (floats) — conflict-free float4 reads
#define VST 260       // v^T row stride
#define PST 260       // per-warp softmax prob stride

#define K_SM_F  (256 * KST)                       // 9216
#define V_SM_F  (32 * VST)                        // 8320
#define P_SM_F  (8 * PST)                         // 2080
#define Q_SM_F  (8 * 32)                          // 256
#define ATTN_SMEM_BYTES ((K_SM_F + V_SM_F + P_SM_F + Q_SM_F) * 4)   // 79488

__global__ void attn_kernel() {
    extern __shared__ float sm[];
    float* k_sm = sm;
    float* v_sm = sm + K_SM_F;
    float* p_sm = sm + K_SM_F + V_SM_F;
    float* q_sm = sm + K_SM_F + V_SM_F + P_SM_F;

    int l = blockIdx.x >> 3;
    int h = blockIdx.x & 7;
    int tid = threadIdx.x;
    int w = tid >> 5, lane = tid & 31;

    size_t head_off = (size_t)h * CDIM;

    // load K (256 x 32) and V^T (32 x 256) into smem
    for (int idx = tid; idx < 256 * 32; idx += 256) {
        int t = idx >> 5, c = idx & 31;
        size_t gi = ((size_t)(t * LRES + l)) * HC + head_off + c;
        k_sm[t * KST + c] = g_k[gi];
        v_sm[c * VST + t] = g_v[gi];
    }
    __syncthreads();

    // each warp owns query rows s = w, w+8, ...
    for (int s = w; s < NSEQ; s += 8) {
        size_t qi = ((size_t)(s * LRES + l)) * HC + head_off + lane;
        q_sm[w * 32 + lane] = g_q[qi];
        __syncwarp();

        float sc[8];
        #pragma unroll
        for (int i = 0; i < 8; i++) {
            int t = i * 32 + lane;
            float acc = 0.0f;
            #pragma unroll
            for (int c4 = 0; c4 < 8; c4++) {
                float4 k4 = *(float4*)&k_sm[t * KST + c4 * 4];
                float4 q4 = *(float4*)&q_sm[w * 32 + c4 * 4];
                acc += k4.x * q4.x + k4.y * q4.y + k4.z * q4.z + k4.w * q4.w;
            }
            sc[i] = acc * SQC;
        }
        // softmax over t (256 values spread 8-per-lane)
        float mx = sc[0];
        #pragma unroll
        for (int i = 1; i < 8; i++) mx = fmaxf(mx, sc[i]);
        #pragma unroll
        for (int o = 16; o; o >>= 1) mx = fmaxf(mx, __shfl_xor_sync(0xffffffffu, mx, o));
        float sum = 0.0f;
        #pragma unroll
        for (int i = 0; i < 8; i++) { sc[i] = __expf(sc[i] - mx); sum += sc[i]; }
        #pragma unroll
        for (int o = 16; o; o >>= 1) sum += __shfl_xor_sync(0xffffffffu, sum, o);
        float rinv = 1.0f / sum;
        #pragma unroll
        for (int i = 0; i < 8; i++) p_sm[w * PST + i * 32 + lane] = sc[i] * rinv;
        __syncwarp();

        // out: lane = channel c;  o[c] = sum_t p[t] * v[t][c]
        float acc = 0.0f;
        #pragma unroll
        for (int t4 = 0; t4 < 64; t4++) {
            float4 p4 = *(float4*)&p_sm[w * PST + t4 * 4];
            float4 v4 = *(float4*)&v_sm[lane * VST + t4 * 4];
            acc += p4.x * v4.x + p4.y * v4.y + p4.z * v4.z + p4.w * v4.w;
        }
        float gv = g_g[qi];
        g_o[qi] = acc * gv;
        __syncwarp();
    }
}

// ============================ launch ============================
extern "C" void kernel_launch(void* const* d_in, const int* in_sizes, int n_in,
                              void* d_out, int out_size) {
    (void)in_sizes; (void)n_in; (void)out_size;
    const float* m     = (const float*)d_in[0];
    const float* gamma = (const float*)d_in[1];
    const float* beta  = (const float*)d_in[2];
    const float* Wq    = (const float*)d_in[3];
    const float* Wk    = (const float*)d_in[4];
    const float* Wv    = (const float*)d_in[5];
    const float* Wg    = (const float*)d_in[6];
    const float* bg    = (const float*)d_in[7];
    const float* Wo    = (const float*)d_in[8];
    const float* bo    = (const float*)d_in[9];
    float* out = (float*)d_out;

    float *x, *q, *k, *v, *g, *o;
    cudaGetSymbolAddress((void**)&x, g_x);
    cudaGetSymbolAddress((void**)&q, g_q);
    cudaGetSymbolAddress((void**)&k, g_k);
    cudaGetSymbolAddress((void**)&v, g_v);
    cudaGetSymbolAddress((void**)&g, g_g);
    cudaGetSymbolAddress((void**)&o, g_o);

    cudaFuncSetAttribute(attn_kernel, cudaFuncAttributeMaxDynamicSharedMemorySize,
                         ATTN_SMEM_BYTES);

    // 1) layernorm
    ln_kernel<<<NL, 64>>>(m, gamma, beta);

    // 2) projections (q, k, v plain; g with sigmoid+bias)
    dim3 ggrid(256 / BN, NL / BM);
    gemm_kernel<<<ggrid, 256>>>(x, Wq, nullptr, q, 0);
    gemm_kernel<<<ggrid, 256>>>(x, Wk, nullptr, k, 0);
    gemm_kernel<<<ggrid, 256>>>(x, Wv, nullptr, v, 0);
    gemm_kernel<<<ggrid, 256>>>(x, Wg, bg,      g, 1);

    // 3) attention per (l, h)
    attn_kernel<<<LRES * NHEAD, 256, ATTN_SMEM_BYTES>>>();

    // 4) output projection + bias
    gemm_kernel<<<ggrid, 256>>>(o, Wo, bo, out, 2);
}

// round 3
// speedup vs baseline: 1.0007x; 1.0001x over previous
#include <cuda_runtime.h>
#include <math.h>

#define NSEQ  256
#define LRES  384
#define MDIM  256
#define NHEAD 8
#define CDIM  32
#define HC    256
#define NL    (NSEQ * LRES)            // 98304
#define SQC   0.17677669529663687f     // 1/sqrt(32)

// -------- scratch (static device globals; no allocations allowed) --------
__device__ float g_x[(size_t)NL * MDIM];   // layernormed input
__device__ float g_q[(size_t)NL * HC];
__device__ float g_k[(size_t)NL * HC];
__device__ float g_v[(size_t)NL * HC];
__device__ float g_g[(size_t)NL * HC];     // sigmoid gate (activation applied)
__device__ float g_o[(size_t)NL * HC];     // gated attention output

// ============================ LayerNorm ============================
// one block (64 threads) per row of 256; float4 per thread
__global__ void ln_kernel(const float* __restrict__ m,
                          const float* __restrict__ gamma,
                          const float* __restrict__ beta) {
    int row = blockIdx.x;
    const float4* mr = (const float4*)(m + (size_t)row * MDIM);
    float4* xr = (float4*)(g_x + (size_t)row * MDIM);
    int tid = threadIdx.x;

    float4 v = mr[tid];
    float s  = v.x + v.y + v.z + v.w;
    float ss = v.x * v.x + v.y * v.y + v.z * v.z + v.w * v.w;
    #pragma unroll
    for (int o = 16; o; o >>= 1) {
        s  += __shfl_xor_sync(0xffffffffu, s,  o);
        ss += __shfl_xor_sync(0xffffffffu, ss, o);
    }
    __shared__ float sh[4];
    if ((tid & 31) == 0) { sh[tid >> 5] = s; sh[2 + (tid >> 5)] = ss; }
    __syncthreads();
    s  = sh[0] + sh[1];
    ss = sh[2] + sh[3];
    float mu  = s * (1.0f / MDIM);
    float var = ss * (1.0f / MDIM) - mu * mu;
    float inv = rsqrtf(var + 1e-5f);

    float4 gm = ((const float4*)gamma)[tid];
    float4 bt = ((const float4*)beta)[tid];
    float4 r;
    r.x = (v.x - mu) * inv * gm.x + bt.x;
    r.y = (v.y - mu) * inv * gm.y + bt.y;
    r.z = (v.z - mu) * inv * gm.z + bt.z;
    r.w = (v.w - mu) * inv * gm.w + bt.w;
    xr[tid] = r;
}

// ============================ GEMM ============================
// C[M,256] = A[M,256] * B[256,256]   (A,B,C row-major)
// epi_mode: 0 plain, 1 sigmoid(v + bias), 2 v + bias
#define BM 64
#define BN 64
#define BK 16
__global__ void gemm_kernel(const float* __restrict__ A,
                            const float* __restrict__ B,
                            const float* __restrict__ bias,
                            float* __restrict__ Cout,
                            int epi_mode) {
    __shared__ float As[BK][BM];
    __shared__ float Bs[BK][BN];

    int bn = blockIdx.x * BN;
    int bm = blockIdx.y * BM;
    int tid = threadIdx.x;                 // 256 threads
    int tx = tid & 15, ty = tid >> 4;

    float acc[4][4] = {};

    int ar = tid >> 2;                     // 0..63 (A row within tile)
    int ac = (tid & 3) << 2;               // 0,4,8,12 (A k-offset)
    int br = tid >> 4;                     // 0..15 (B k within tile)
    int bc = (tid & 15) << 2;              // B col offset

    for (int k0 = 0; k0 < 256; k0 += BK) {
        float4 a4 = *(const float4*)&A[(size_t)(bm + ar) * 256 + k0 + ac];
        As[ac + 0][ar] = a4.x;
        As[ac + 1][ar] = a4.y;
        As[ac + 2][ar] = a4.z;
        As[ac + 3][ar] = a4.w;
        *(float4*)&Bs[br][bc] = *(const float4*)&B[(size_t)(k0 + br) * 256 + bn + bc];
        __syncthreads();

        #pragma unroll
        for (int kk = 0; kk < BK; kk++) {
            float4 a = *(float4*)&As[kk][ty << 2];
            float4 b = *(float4*)&Bs[kk][tx << 2];
            acc[0][0] += a.x * b.x; acc[0][1] += a.x * b.y; acc[0][2] += a.x * b.z; acc[0][3] += a.x * b.w;
            acc[1][0] += a.y * b.x; acc[1][1] += a.y * b.y; acc[1][2] += a.y * b.z; acc[1][3] += a.y * b.w;
            acc[2][0] += a.z * b.x; acc[2][1] += a.z * b.y; acc[2][2] += a.z * b.z; acc[2][3] += a.z * b.w;
            acc[3][0] += a.w * b.x; acc[3][1] += a.w * b.y; acc[3][2] += a.w * b.z; acc[3][3] += a.w * b.w;
        }
        __syncthreads();
    }

    #pragma unroll
    for (int i = 0; i < 4; i++) {
        int row = bm + (ty << 2) + i;
        #pragma unroll
        for (int j = 0; j < 4; j++) {
            int col = bn + (tx << 2) + j;
            float val = acc[i][j];
            if (epi_mode == 1)      val = 1.0f / (1.0f + expf(-(val + bias[col])));
            else if (epi_mode == 2) val += bias[col];
            Cout[(size_t)row * 256 + col] = val;
        }
    }
}

// ============================ Attention ============================
// one CTA (256 threads = 8 warps) per (l, h). K and V^T resident in smem.
#define KST 36        // k_sm row stride (floats) — conflict-free float4 reads
#define VST 260       // v^T row stride
#define PST 260       // per-warp softmax prob stride

#define K_SM_F  (256 * KST)                       // 9216
#define V_SM_F  (32 * VST)                        // 8320
#define P_SM_F  (8 * PST)                         // 2080
#define Q_SM_F  (8 * 32)                          // 256
#define ATTN_SMEM_BYTES ((K_SM_F + V_SM_F + P_SM_F + Q_SM_F) * 4)   // 79488

__global__ void attn_kernel() {
    extern __shared__ float sm[];
    float* k_sm = sm;
    float* v_sm = sm + K_SM_F;
    float* p_sm = sm + K_SM_F + V_SM_F;
    float* q_sm = sm + K_SM_F + V_SM_F + P_SM_F;

    int l = blockIdx.x >> 3;
    int h = blockIdx.x & 7;
    int tid = threadIdx.x;
    int w = tid >> 5, lane = tid & 31;

    size_t head_off = (size_t)h * CDIM;

    // load K (256 x 32) and V^T (32 x 256) into smem
    for (int idx = tid; idx < 256 * 32; idx += 256) {
        int t = idx >> 5, c = idx & 31;
        size_t gi = ((size_t)(t * LRES + l)) * HC + head_off + c;
        k_sm[t * KST + c] = g_k[gi];
        v_sm[c * VST + t] = g_v[gi];
    }
    __syncthreads();

    // each warp owns query rows s = w, w+8, ...
    for (int s = w; s < NSEQ; s += 8) {
        size_t qi = ((size_t)(s * LRES + l)) * HC + head_off + lane;
        q_sm[w * 32 + lane] = g_q[qi];
        __syncwarp();

        float sc[8];
        #pragma unroll
        for (int i = 0; i < 8; i++) {
            int t = i * 32 + lane;
            float acc = 0.0f;
            #pragma unroll
            for (int c4 = 0; c4 < 8; c4++) {
                float4 k4 = *(float4*)&k_sm[t * KST + c4 * 4];
                float4 q4 = *(float4*)&q_sm[w * 32 + c4 * 4];
                acc += k4.x * q4.x + k4.y * q4.y + k4.z * q4.z + k4.w * q4.w;
            }
            sc[i] = acc * SQC;
        }
        // softmax over t (256 values spread 8-per-lane)
        float mx = sc[0];
        #pragma unroll
        for (int i = 1; i < 8; i++) mx = fmaxf(mx, sc[i]);
        #pragma unroll
        for (int o = 16; o; o >>= 1) mx = fmaxf(mx, __shfl_xor_sync(0xffffffffu, mx, o));
        float sum = 0.0f;
        #pragma unroll
        for (int i = 0; i < 8; i++) { sc[i] = __expf(sc[i] - mx); sum += sc[i]; }
        #pragma unroll
        for (int o = 16; o; o >>= 1) sum += __shfl_xor_sync(0xffffffffu, sum, o);
        float rinv = 1.0f / sum;
        #pragma unroll
        for (int i = 0; i < 8; i++) p_sm[w * PST + i * 32 + lane] = sc[i] * rinv;
        __syncwarp();

        // out: lane = channel c;  o[c] = sum_t p[t] * v[t][c]
        float acc = 0.0f;
        #pragma unroll
        for (int t4 = 0; t4 < 64; t4++) {
            float4 p4 = *(float4*)&p_sm[w * PST + t4 * 4];
            float4 v4 = *(float4*)&v_sm[lane * VST + t4 * 4];
            acc += p4.x * v4.x + p4.y * v4.y + p4.z * v4.z + p4.w * v4.w;
        }
        float gv = g_g[qi];
        g_o[qi] = acc * gv;
        __syncwarp();
    }
}

// ============================ launch ============================
extern "C" void kernel_launch(void* const* d_in, const int* in_sizes, int n_in,
                              void* d_out, int out_size) {
    (void)in_sizes; (void)n_in; (void)out_size;
    const float* m     = (const float*)d_in[0];
    const float* gamma = (const float*)d_in[1];
    const float* beta  = (const float*)d_in[2];
    const float* Wq    = (const float*)d_in[3];
    const float* Wk    = (const float*)d_in[4];
    const float* Wv    = (const float*)d_in[5];
    const float* Wg    = (const float*)d_in[6];
    const float* bg    = (const float*)d_in[7];
    const float* Wo    = (const float*)d_in[8];
    const float* bo    = (const float*)d_in[9];
    float* out = (float*)d_out;

    float *x, *q, *k, *v, *g, *o;
    cudaGetSymbolAddress((void**)&x, g_x);
    cudaGetSymbolAddress((void**)&q, g_q);
    cudaGetSymbolAddress((void**)&k, g_k);
    cudaGetSymbolAddress((void**)&v, g_v);
    cudaGetSymbolAddress((void**)&g, g_g);
    cudaGetSymbolAddress((void**)&o, g_o);

    cudaFuncSetAttribute(attn_kernel, cudaFuncAttributeMaxDynamicSharedMemorySize,
                         ATTN_SMEM_BYTES);

    // 1) layernorm
    ln_kernel<<<NL, 64>>>(m, gamma, beta);

    // 2) projections (q, k, v plain; g with sigmoid+bias)
    dim3 ggrid(256 / BN, NL / BM);
    gemm_kernel<<<ggrid, 256>>>(x, Wq, nullptr, q, 0);
    gemm_kernel<<<ggrid, 256>>>(x, Wk, nullptr, k, 0);
    gemm_kernel<<<ggrid, 256>>>(x, Wv, nullptr, v, 0);
    gemm_kernel<<<ggrid, 256>>>(x, Wg, bg,      g, 1);

    // 3) attention per (l, h)
    attn_kernel<<<LRES * NHEAD, 256, ATTN_SMEM_BYTES>>>();

    // 4) output projection + bias
    gemm_kernel<<<ggrid, 256>>>(o, Wo, bo, out, 2);
}